// round 1
// baseline (speedup 1.0000x reference)
#include <cuda_runtime.h>
#include <math.h>

// Problem constants (fixed by the dataset)
#define NPTS 65536
#define CH   128
#define NCLS 10
#define KNBR 27
#define OUTC 17   // 1 (ctr) + 6 (reg) + 10 (cls)

// sigmoid(s) > 0.15  <=>  s > log(0.15/0.85)
#define THRESH_LOGIT -1.7346010553881064f

// Scratch (allocation-free rule: __device__ globals)
__device__ int  g_count;
__device__ int2 g_pairs[NPTS * NCLS];   // worst case every (class,point) passes

__device__ __forceinline__ float elu1(float x) {
    return x > 0.f ? x : (expf(x) - 1.f);
}

// ---------------------------------------------------------------------------
// Kernel 0: zero-fill the output (poisoned by harness) + reset pair counter.
// Runs first in stream order so the counter is 0 before k_sem's atomics.
// ---------------------------------------------------------------------------
__global__ void k_zero(float* __restrict__ out, long long nelem) {
    long long n4 = nelem >> 2;
    float4* out4 = reinterpret_cast<float4*>(out);
    long long idx    = (long long)blockIdx.x * blockDim.x + threadIdx.x;
    long long stride = (long long)gridDim.x * blockDim.x;
    const float4 z = make_float4(0.f, 0.f, 0.f, 0.f);
    for (long long t = idx; t < n4; t += stride) out4[t] = z;
    // scalar tail (nelem % 4)
    for (long long t = (n4 << 2) + idx; t < nelem; t += stride) out[t] = 0.f;
    if (blockIdx.x == 0 && threadIdx.x == 0) g_count = 0;
}

// ---------------------------------------------------------------------------
// Kernel 1: sem = feats @ Wsem + bsem ; compact (class, point) pairs whose
// sigmoid(sem) > 0.15. One warp per point, float4 coalesced feats reads.
// ---------------------------------------------------------------------------
__global__ void k_sem(const float* __restrict__ feats,
                      const float* __restrict__ Wsem,
                      const float* __restrict__ bsem) {
    __shared__ float sW[CH * NCLS];
    const int tid = threadIdx.x;
    for (int t = tid; t < CH * NCLS; t += blockDim.x) sW[t] = Wsem[t];
    __syncthreads();

    const int warp = tid >> 5;
    const int lane = tid & 31;
    const int i = blockIdx.x * (blockDim.x >> 5) + warp;
    if (i >= NPTS) return;

    // each lane handles 4 consecutive channels
    float4 f = reinterpret_cast<const float4*>(feats + (long long)i * CH)[lane];
    const int m = lane * 4;
    float s[NCLS];
#pragma unroll
    for (int c = 0; c < NCLS; c++) {
        s[c] = f.x * sW[(m + 0) * NCLS + c]
             + f.y * sW[(m + 1) * NCLS + c]
             + f.z * sW[(m + 2) * NCLS + c]
             + f.w * sW[(m + 3) * NCLS + c];
    }
#pragma unroll
    for (int off = 16; off; off >>= 1)
#pragma unroll
        for (int c = 0; c < NCLS; c++)
            s[c] += __shfl_xor_sync(0xffffffffu, s[c], off);

    if (lane == 0) {
#pragma unroll
        for (int c = 0; c < NCLS; c++) {
            if (s[c] + bsem[c] > THRESH_LOGIT) {
                int pos = atomicAdd(&g_count, 1);
                g_pairs[pos] = make_int2(c, i);
            }
        }
    }
}

// ---------------------------------------------------------------------------
// Kernel 2: full head pipeline, but ONLY for compacted (class, point) pairs.
// One 128-thread block per pair (grid-stride over pairs). Normally g_count==0
// and every block exits after one global load.
// ---------------------------------------------------------------------------
__global__ void k_heads(const float* __restrict__ feats,
                        const int*   __restrict__ nbr,
                        const float* __restrict__ fo_w,
                        const float* __restrict__ fo_g,
                        const float* __restrict__ fo_b,
                        const float* __restrict__ cls_out_w,
                        const float* __restrict__ cls_out_g,
                        const float* __restrict__ cls_out_b,
                        const float* __restrict__ up_w,
                        const float* __restrict__ up_g,
                        const float* __restrict__ up_b,
                        const float* __restrict__ fuse_w,
                        const float* __restrict__ fuse_g,
                        const float* __restrict__ fuse_b,
                        const float* __restrict__ exp_w,
                        const float* __restrict__ exp_g,
                        const float* __restrict__ exp_b,
                        const float* __restrict__ ctr_w,
                        const float* __restrict__ reg_w,
                        const float* __restrict__ cls_w,
                        const float* __restrict__ cls_b,
                        const float* __restrict__ scales,
                        float* __restrict__ out) {
    __shared__ float sx[CH];        // stage input
    __shared__ float cat[2 * CH];   // [hc | uc]
    __shared__ float sec[CH];       // expand_out
    __shared__ float sof[CH];       // offset_features for this point

    const int j = threadIdx.x;      // output channel owned by this thread
    const int npairs = g_count;

    for (int p = blockIdx.x; p < npairs; p += gridDim.x) {
        const int c = g_pairs[p].x;
        const int i = g_pairs[p].y;

        // --- offset_features[i] = ELU(affine(sum_k feats[nbr[i,k]] @ fo_w[k])) ---
        float acc = 0.f;
        for (int k = 0; k < KNBR; k++) {
            const int nb = nbr[i * KNBR + k];
            __syncthreads();
            sx[j] = feats[(long long)nb * CH + j];
            __syncthreads();
            const float* W = fo_w + (long long)k * CH * CH;
            for (int m = 0; m < CH; m++) acc += sx[m] * W[m * CH + j];
        }
        sof[j] = elu1(acc * fo_g[j] + fo_b[j]);

        // --- two rows: row i uses offset_features, row N+i uses feats[i] ---
        for (int half = 0; half < 2; half++) {
            __syncthreads();
            sx[j] = (half == 0) ? sof[j] : feats[(long long)i * CH + j];
            __syncthreads();

            // hc
            {
                const float* W = cls_out_w + (long long)c * CH * CH;
                float a = 0.f;
                for (int m = 0; m < CH; m++) a += sx[m] * W[m * CH + j];
                a = a * cls_out_g[c * CH + j] + cls_out_b[c * CH + j];
                cat[j] = elu1(a);
            }
            __syncthreads();
            // uc
            {
                const float* W = up_w + (long long)c * CH * CH;
                float a = 0.f;
                for (int m = 0; m < CH; m++) a += cat[m] * W[m * CH + j];
                a = a * up_g[c * CH + j] + up_b[c * CH + j];
                cat[CH + j] = elu1(a);
            }
            __syncthreads();
            // fc = ELU(affine(concat(hc,uc) @ fuse_w[c]))
            float fc;
            {
                const float* W = fuse_w + (long long)c * 2 * CH * CH;
                float a = 0.f;
                for (int m = 0; m < 2 * CH; m++) a += cat[m] * W[m * CH + j];
                a = a * fuse_g[c * CH + j] + fuse_b[c * CH + j];
                fc = elu1(a);
            }
            __syncthreads();
            sx[j] = fc;
            __syncthreads();
            // ec
            {
                const float* W = exp_w + (long long)c * CH * CH;
                float a = 0.f;
                for (int m = 0; m < CH; m++) a += sx[m] * W[m * CH + j];
                a = a * exp_g[c * CH + j] + exp_b[c * CH + j];
                sec[j] = elu1(a);
            }
            __syncthreads();

            // outputs: 17 columns, threads 0..16 each do one 128-dot
            const long long row = (half == 0) ? (long long)i : (long long)(NPTS + i);
            float* orow = out + ((long long)c * 2 * NPTS + row) * OUTC;
            if (j == 0) {
                float s = 0.f;
                for (int m = 0; m < CH; m++) s += sec[m] * ctr_w[m];
                orow[0] = s;                                   // ctr (mask==1)
            } else if (j < 7) {
                const int r = j - 1;
                float s = 0.f;
                for (int m = 0; m < CH; m++) s += sec[m] * reg_w[m * 6 + r];
                orow[j] = expf(scales[c] * s);                 // reg
            } else if (j < 17) {
                const int q = j - 7;
                float s = 0.f;
                for (int m = 0; m < CH; m++) s += sec[m] * cls_w[m * NCLS + q];
                orow[j] = s + cls_b[q];                        // cls
            }
        }
    }
}

// ---------------------------------------------------------------------------
// Launch. Input order per metadata: coords, feats, nbr, Wsem, bsem,
// off_w1,g1,b1, off_w2,g2,b2, off_w3, fo_w,g,b, cls_out_w,g,b, up_w,g,b,
// fuse_w,g,b, exp_w,g,b, ctr_w, reg_w, cls_w, cls_b, scales.
// The offset-MLP branch (5..11) and coords (0) are dead w.r.t. the output.
// ---------------------------------------------------------------------------
extern "C" void kernel_launch(void* const* d_in, const int* in_sizes, int n_in,
                              void* d_out, int out_size) {
    const float* feats     = (const float*)d_in[1];
    const int*   nbr       = (const int*)  d_in[2];
    const float* Wsem      = (const float*)d_in[3];
    const float* bsem      = (const float*)d_in[4];
    const float* fo_w      = (const float*)d_in[12];
    const float* fo_g      = (const float*)d_in[13];
    const float* fo_b      = (const float*)d_in[14];
    const float* cls_out_w = (const float*)d_in[15];
    const float* cls_out_g = (const float*)d_in[16];
    const float* cls_out_b = (const float*)d_in[17];
    const float* up_w      = (const float*)d_in[18];
    const float* up_g      = (const float*)d_in[19];
    const float* up_b      = (const float*)d_in[20];
    const float* fuse_w    = (const float*)d_in[21];
    const float* fuse_g    = (const float*)d_in[22];
    const float* fuse_b    = (const float*)d_in[23];
    const float* exp_w     = (const float*)d_in[24];
    const float* exp_g     = (const float*)d_in[25];
    const float* exp_b     = (const float*)d_in[26];
    const float* ctr_w     = (const float*)d_in[27];
    const float* reg_w     = (const float*)d_in[28];
    const float* cls_w     = (const float*)d_in[29];
    const float* cls_b     = (const float*)d_in[30];
    const float* scales    = (const float*)d_in[31];
    float* out = (float*)d_out;

    const long long nelem = (long long)out_size;

    // K0: zero output + reset counter (ordering in-stream guarantees the reset
    // lands before k_sem's atomics).
    {
        long long n4 = nelem >> 2;
        int blocks = (int)((n4 + 255) / 256);
        if (blocks > 4096) blocks = 4096;
        if (blocks < 1) blocks = 1;
        k_zero<<<blocks, 256>>>(out, nelem);
    }
    // K1: semantic gating + compaction (8 points per 256-thread block)
    k_sem<<<NPTS / 8, 256>>>(feats, Wsem, bsem);
    // K2: lazy heads over compacted pairs
    k_heads<<<256, 128>>>(feats, nbr, fo_w, fo_g, fo_b,
                          cls_out_w, cls_out_g, cls_out_b,
                          up_w, up_g, up_b,
                          fuse_w, fuse_g, fuse_b,
                          exp_w, exp_g, exp_b,
                          ctr_w, reg_w, cls_w, cls_b, scales, out);
}

// round 2
// speedup vs baseline: 1.3647x; 1.3647x over previous
#include <cuda_runtime.h>
#include <math.h>

// Problem constants (fixed by the dataset)
#define NPTS 65536
#define CH   128
#define NCLS 10
#define KNBR 27
#define OUTC 17   // 1 (ctr) + 6 (reg) + 10 (cls)

// sigmoid(s) > 0.15  <=>  s > log(0.15/0.85)
#define THRESH_LOGIT -1.7346010553881064f

// Fused-kernel block split
#define SBLOCKS 1024                      // sem blocks
#define ZBLOCKS 3072                      // zero-fill blocks
#define PTS_PER_SBLOCK (NPTS / SBLOCKS)   // 64 points per sem block (8 warps x 8 iters)

// Per-point class bitmask (bit c set <=> sigmoid(sem[p,c]) > 0.15).
// Written unconditionally every replay -> no counter, no reset ordering.
__device__ unsigned short g_mask[NPTS];

__device__ __forceinline__ float elu1(float x) {
    return x > 0.f ? x : (expf(x) - 1.f);
}

// ---------------------------------------------------------------------------
// Kernel 1 (fused): low block IDs compute sem + class mask; high block IDs
// zero-fill the poisoned output. Disjoint data -> memory system overlaps both.
// ---------------------------------------------------------------------------
__global__ void k_fused(const float* __restrict__ feats,
                        const float* __restrict__ Wsem,
                        const float* __restrict__ bsem,
                        float* __restrict__ out,
                        long long nelem) {
    if (blockIdx.x < SBLOCKS) {
        // ---- sem mask blocks ----
        // Wsem staged transposed as float4: sWt[c*32 + g] = W[4g..4g+3][c]
        __shared__ float4 sWt[NCLS * 32];
        __shared__ float  sThr[NCLS];
        const int tid = threadIdx.x;
        if (tid < NCLS * 32) {
            const int c = tid >> 5, g = tid & 31;
            sWt[tid] = make_float4(Wsem[(4 * g + 0) * NCLS + c],
                                   Wsem[(4 * g + 1) * NCLS + c],
                                   Wsem[(4 * g + 2) * NCLS + c],
                                   Wsem[(4 * g + 3) * NCLS + c]);
        }
        if (tid < NCLS) sThr[tid] = THRESH_LOGIT - bsem[tid];
        __syncthreads();

        const int warp = tid >> 5;
        const int lane = tid & 31;
        const int base = blockIdx.x * PTS_PER_SBLOCK;

#pragma unroll
        for (int it = 0; it < PTS_PER_SBLOCK / 8; it++) {
            const int p = base + it * 8 + warp;
            // coalesced: lane reads channels [4*lane, 4*lane+3]
            const float4 f = reinterpret_cast<const float4*>(feats)[p * 32 + lane];
            float s[NCLS];
#pragma unroll
            for (int c = 0; c < NCLS; c++) {
                const float4 w = sWt[c * 32 + lane];       // conflict-free LDS.128
                s[c] = f.x * w.x + f.y * w.y + f.z * w.z + f.w * w.w;
            }
#pragma unroll
            for (int off = 16; off; off >>= 1)
#pragma unroll
                for (int c = 0; c < NCLS; c++)
                    s[c] += __shfl_xor_sync(0xffffffffu, s[c], off);

            if (lane == 0) {
                unsigned m = 0;
#pragma unroll
                for (int c = 0; c < NCLS; c++)
                    if (s[c] > sThr[c]) m |= (1u << c);
                g_mask[p] = (unsigned short)m;
            }
        }
    } else {
        // ---- zero-fill blocks ----
        const long long idx = (long long)(blockIdx.x - SBLOCKS) * blockDim.x + threadIdx.x;
        const long long stride = (long long)ZBLOCKS * blockDim.x;
        const long long n4 = nelem >> 2;
        float4* out4 = reinterpret_cast<float4*>(out);
        const float4 z = make_float4(0.f, 0.f, 0.f, 0.f);
#pragma unroll 4
        for (long long t = idx; t < n4; t += stride) out4[t] = z;
        for (long long t = (n4 << 2) + idx; t < nelem; t += stride) out[t] = 0.f;
    }
}

// ---------------------------------------------------------------------------
// Kernel 2: scan class masks; run the full head pipeline only for flagged
// (point, class) pairs. Normally every block exits after one 256B scan.
// 512 blocks x 128 threads; block b owns points [b*128, b*128+128).
// ---------------------------------------------------------------------------
__global__ void k_heads(const float* __restrict__ feats,
                        const int*   __restrict__ nbr,
                        const float* __restrict__ fo_w,
                        const float* __restrict__ fo_g,
                        const float* __restrict__ fo_b,
                        const float* __restrict__ cls_out_w,
                        const float* __restrict__ cls_out_g,
                        const float* __restrict__ cls_out_b,
                        const float* __restrict__ up_w,
                        const float* __restrict__ up_g,
                        const float* __restrict__ up_b,
                        const float* __restrict__ fuse_w,
                        const float* __restrict__ fuse_g,
                        const float* __restrict__ fuse_b,
                        const float* __restrict__ exp_w,
                        const float* __restrict__ exp_g,
                        const float* __restrict__ exp_b,
                        const float* __restrict__ ctr_w,
                        const float* __restrict__ reg_w,
                        const float* __restrict__ cls_w,
                        const float* __restrict__ cls_b,
                        const float* __restrict__ scales,
                        float* __restrict__ out) {
    __shared__ unsigned short smask[128];
    __shared__ float sx[CH];        // stage input
    __shared__ float cat[2 * CH];   // [hc | uc]
    __shared__ float sec[CH];       // expand_out
    __shared__ float sof[CH];       // offset_features for this point

    const int j = threadIdx.x;
    const int base = blockIdx.x * 128;

    smask[j] = g_mask[base + j];
    const int any = __syncthreads_or(smask[j] != 0);
    if (!any) return;                       // the hot path: one scan, done

    for (int t = 0; t < 128; t++) {
        unsigned m = smask[t];
        if (!m) continue;
        const int i = base + t;

        // --- offset_features[i] = ELU(affine(sum_k feats[nbr[i,k]] @ fo_w[k])) ---
        float acc = 0.f;
        for (int k = 0; k < KNBR; k++) {
            const int nb = nbr[i * KNBR + k];
            __syncthreads();
            sx[j] = feats[(long long)nb * CH + j];
            __syncthreads();
            const float* W = fo_w + (long long)k * CH * CH;
            for (int mm = 0; mm < CH; mm++) acc += sx[mm] * W[mm * CH + j];
        }
        sof[j] = elu1(acc * fo_g[j] + fo_b[j]);

        while (m) {
            const int c = __ffs(m) - 1;
            m &= (m - 1);

            // --- two rows: row i uses offset_features, row N+i uses feats[i] ---
            for (int half = 0; half < 2; half++) {
                __syncthreads();
                sx[j] = (half == 0) ? sof[j] : feats[(long long)i * CH + j];
                __syncthreads();

                // hc
                {
                    const float* W = cls_out_w + (long long)c * CH * CH;
                    float a = 0.f;
                    for (int mm = 0; mm < CH; mm++) a += sx[mm] * W[mm * CH + j];
                    a = a * cls_out_g[c * CH + j] + cls_out_b[c * CH + j];
                    cat[j] = elu1(a);
                }
                __syncthreads();
                // uc
                {
                    const float* W = up_w + (long long)c * CH * CH;
                    float a = 0.f;
                    for (int mm = 0; mm < CH; mm++) a += cat[mm] * W[mm * CH + j];
                    a = a * up_g[c * CH + j] + up_b[c * CH + j];
                    cat[CH + j] = elu1(a);
                }
                __syncthreads();
                // fc
                float fc;
                {
                    const float* W = fuse_w + (long long)c * 2 * CH * CH;
                    float a = 0.f;
                    for (int mm = 0; mm < 2 * CH; mm++) a += cat[mm] * W[mm * CH + j];
                    a = a * fuse_g[c * CH + j] + fuse_b[c * CH + j];
                    fc = elu1(a);
                }
                __syncthreads();
                sx[j] = fc;
                __syncthreads();
                // ec
                {
                    const float* W = exp_w + (long long)c * CH * CH;
                    float a = 0.f;
                    for (int mm = 0; mm < CH; mm++) a += sx[mm] * W[mm * CH + j];
                    a = a * exp_g[c * CH + j] + exp_b[c * CH + j];
                    sec[j] = elu1(a);
                }
                __syncthreads();

                // outputs: 17 columns, threads 0..16 each do one 128-dot
                const long long row = (half == 0) ? (long long)i : (long long)(NPTS + i);
                float* orow = out + ((long long)c * 2 * NPTS + row) * OUTC;
                if (j == 0) {
                    float s = 0.f;
                    for (int mm = 0; mm < CH; mm++) s += sec[mm] * ctr_w[mm];
                    orow[0] = s;                                   // ctr
                } else if (j < 7) {
                    const int r = j - 1;
                    float s = 0.f;
                    for (int mm = 0; mm < CH; mm++) s += sec[mm] * reg_w[mm * 6 + r];
                    orow[j] = expf(scales[c] * s);                 // reg
                } else if (j < 17) {
                    const int q = j - 7;
                    float s = 0.f;
                    for (int mm = 0; mm < CH; mm++) s += sec[mm] * cls_w[mm * NCLS + q];
                    orow[j] = s + cls_b[q];                        // cls
                }
            }
        }
    }
}

// ---------------------------------------------------------------------------
// Launch. Input order per metadata: coords, feats, nbr, Wsem, bsem,
// off_w1,g1,b1, off_w2,g2,b2, off_w3, fo_w,g,b, cls_out_w,g,b, up_w,g,b,
// fuse_w,g,b, exp_w,g,b, ctr_w, reg_w, cls_w, cls_b, scales.
// The offset-MLP branch (5..11) and coords (0) are dead w.r.t. the output.
// ---------------------------------------------------------------------------
extern "C" void kernel_launch(void* const* d_in, const int* in_sizes, int n_in,
                              void* d_out, int out_size) {
    const float* feats     = (const float*)d_in[1];
    const int*   nbr       = (const int*)  d_in[2];
    const float* Wsem      = (const float*)d_in[3];
    const float* bsem      = (const float*)d_in[4];
    const float* fo_w      = (const float*)d_in[12];
    const float* fo_g      = (const float*)d_in[13];
    const float* fo_b      = (const float*)d_in[14];
    const float* cls_out_w = (const float*)d_in[15];
    const float* cls_out_g = (const float*)d_in[16];
    const float* cls_out_b = (const float*)d_in[17];
    const float* up_w      = (const float*)d_in[18];
    const float* up_g      = (const float*)d_in[19];
    const float* up_b      = (const float*)d_in[20];
    const float* fuse_w    = (const float*)d_in[21];
    const float* fuse_g    = (const float*)d_in[22];
    const float* fuse_b    = (const float*)d_in[23];
    const float* exp_w     = (const float*)d_in[24];
    const float* exp_g     = (const float*)d_in[25];
    const float* exp_b     = (const float*)d_in[26];
    const float* ctr_w     = (const float*)d_in[27];
    const float* reg_w     = (const float*)d_in[28];
    const float* cls_w     = (const float*)d_in[29];
    const float* cls_b     = (const float*)d_in[30];
    const float* scales    = (const float*)d_in[31];
    float* out = (float*)d_out;

    const long long nelem = (long long)out_size;

    // K1: fused sem-mask + output zero-fill
    k_fused<<<SBLOCKS + ZBLOCKS, 256>>>(feats, Wsem, bsem, out, nelem);

    // K2: lazy heads over flagged (point, class) pairs
    k_heads<<<NPTS / 128, 128>>>(feats, nbr, fo_w, fo_g, fo_b,
                                 cls_out_w, cls_out_g, cls_out_b,
                                 up_w, up_g, up_b,
                                 fuse_w, fuse_g, fuse_b,
                                 exp_w, exp_g, exp_b,
                                 ctr_w, reg_w, cls_w, cls_b, scales, out);
}